// round 4
// baseline (speedup 1.0000x reference)
#include <cuda_runtime.h>
#include <math.h>

#define NBATCH 1024
#define NSEQ   200
#define NROWS  (NBATCH*NSEQ)   /* 204800 */

/* ------------ static scratch (no allocations allowed) ------------ */
__device__ float g_enc [NROWS*128];           /* encoder output                   */
__device__ float g_xpre[NROWS*1024];          /* gate preacts, [r][h8*128+g*32+u] */
__device__ float g_hseq[NSEQ*NBATCH*256];     /* hx per step (output GEMM input)  */
__device__ float g_predpart[2][8*NBATCH*2];   /* parity-buffered pred partials    */

typedef unsigned long long u64;

__device__ __forceinline__ u64 pack2(float lo, float hi){
    u64 r; asm("mov.b64 %0,{%1,%2};" : "=l"(r) : "f"(lo), "f"(hi)); return r;
}
__device__ __forceinline__ void unpack2(u64 v, float& lo, float& hi){
    asm("mov.b64 {%0,%1},%2;" : "=f"(lo), "=f"(hi) : "l"(v));
}
__device__ __forceinline__ u64 fma2(u64 a, u64 b, u64 c){
    u64 d; asm("fma.rn.f32x2 %0,%1,%2,%3;" : "=l"(d) : "l"(a), "l"(b), "l"(c)); return d;
}
__device__ __forceinline__ float sigmoidf_(float x){
    return __fdividef(1.0f, 1.0f + __expf(-x));
}

/* ================= Kernel 1: per-(b,t) set encoder ================= */
__global__ void enc_kernel(const float* __restrict__ coords,
                           const float* __restrict__ W_e1, const float* __restrict__ b_e1,
                           const float* __restrict__ W_e2, const float* __restrict__ b_e2)
{
    int rl = threadIdx.x >> 6;
    int j  = threadIdx.x & 63;
    size_t r = (size_t)blockIdx.x * 4 + rl;

    __shared__ float pt[4][44];
    __shared__ float m [4][2][64];

    if (j < 44) pt[rl][j] = coords[r*88 + ((j>>1)<<2) + (j&1)];
    __syncthreads();

    float w0 = W_e1[j], w1 = W_e1[64+j], bb = b_e1[j];
    float s1 = 0.f, s2 = 0.f;
#pragma unroll
    for (int p = 0; p < 11; p++){
        float hh = fmaf(pt[rl][2*p+1], w1, fmaf(pt[rl][2*p], w0, bb));
        s1 += fmaxf(hh, 0.f);
    }
#pragma unroll
    for (int p = 11; p < 22; p++){
        float hh = fmaf(pt[rl][2*p+1], w1, fmaf(pt[rl][2*p], w0, bb));
        s2 += fmaxf(hh, 0.f);
    }
    m[rl][0][j] = s1 * (1.0f/11.0f);
    m[rl][1][j] = s2 * (1.0f/11.0f);
    __syncthreads();

    float o1 = b_e2[j], o2 = b_e2[j];
#pragma unroll
    for (int k = 0; k < 64; k++){
        float w = W_e2[k*64 + j];
        o1 = fmaf(m[rl][0][k], w, o1);
        o2 = fmaf(m[rl][1][k], w, o2);
    }
    g_enc[r*128 + j]      = o1;
    g_enc[r*128 + 64 + j] = o2;
}

/* ================= Kernel 2: Xpre GEMM =================
   Stores g_xpre[r][col'] with col' = (h16>>1)*128 + g*32 + (h16&1)*16 + j
   so the rnn consumer (h8 = h16>>1 tiles of 32 units) reads one
   contiguous 128-float block per row.                                 */
__global__ void __launch_bounds__(256) xpre_kernel(
    const float* __restrict__ coords, const float* __restrict__ W_ih,
    const float* __restrict__ b_ih,   const float* __restrict__ b_hh)
{
    extern __shared__ float smx[];
    float* a_s = smx;            /* 32*132 = 4224 */
    float* w_s = a_s + 4224;     /* 32*64  = 2048 */
    float* epi = w_s + 2048;     /* 128*65 = 8320 */

    int h  = blockIdx.x;                 /* h16: 16 tiles of 16 units */
    size_t m0 = (size_t)blockIdx.y * 128;
    int tid = threadIdx.x;
    int tb = tid & 31, tu = tid >> 5;

    u64 acc2[4][4];
#pragma unroll
    for (int bi=0;bi<4;bi++)
#pragma unroll
        for (int g=0;g<4;g++) acc2[bi][g] = 0ULL;

    for (int k0 = 0; k0 < 172; k0 += 32){
#pragma unroll
        for (int i = 0; i < 16; i++){
            int li  = tid + i*256;
            int kk  = li & 31, row = li >> 5;
            int k   = k0 + kk;
            float v = 0.f;
            size_t r = m0 + row;
            if (k < 44)       v = coords[r*88 + ((k>>1)<<2) + (k&1)];
            else if (k < 172) v = g_enc[r*128 + (k-44)];
            a_s[kk*132 + row] = v;
        }
#pragma unroll
        for (int i = 0; i < 8; i++){
            int li = tid + i*256;
            int c  = li & 63, kk = li >> 6;
            int k  = k0 + kk;
            float v = 0.f;
            if (k < 172){
                int col = ((c>>4)<<8) + (h<<4) + (c&15);
                v = W_ih[k*1024 + col];
            }
            w_s[kk*64 + c] = v;
        }
        __syncthreads();
#pragma unroll
        for (int kk = 0; kk < 32; kk++){
            float4 a = *(const float4*)&a_s[kk*132 + 4*tb];
            u64 ax = pack2(a.x,a.x), ay = pack2(a.y,a.y);
            u64 az = pack2(a.z,a.z), aw = pack2(a.w,a.w);
            int kw = kk*64 + (tu<<1);
#pragma unroll
            for (int g = 0; g < 4; g++){
                u64 w2 = *(const u64*)&w_s[kw + g*16];
                acc2[0][g] = fma2(ax, w2, acc2[0][g]);
                acc2[1][g] = fma2(ay, w2, acc2[1][g]);
                acc2[2][g] = fma2(az, w2, acc2[2][g]);
                acc2[3][g] = fma2(aw, w2, acc2[3][g]);
            }
        }
        __syncthreads();
    }

#pragma unroll
    for (int g = 0; g < 4; g++){
        int col0 = (g<<8) + (h<<4) + 2*tu;
        float b0 = b_ih[col0]   + b_hh[col0];
        float b1 = b_ih[col0+1] + b_hh[col0+1];
#pragma unroll
        for (int bi = 0; bi < 4; bi++){
            float lo, hi; unpack2(acc2[bi][g], lo, hi);
            epi[(4*tb+bi)*65 + g*16 + 2*tu]     = lo + b0;
            epi[(4*tb+bi)*65 + g*16 + 2*tu + 1] = hi + b1;
        }
    }
    __syncthreads();
#pragma unroll
    for (int i = 0; i < 8; i++){
        int li = tid + i*256;
        int row = li >> 4, c4 = li & 15;
        size_t r = m0 + row;
        int colp = (h>>1)*128 + (c4>>2)*32 + (h&1)*16 + (c4&3)*4;
        float4 v = make_float4(epi[row*65 + 4*c4],   epi[row*65 + 4*c4+1],
                               epi[row*65 + 4*c4+2], epi[row*65 + 4*c4+3]);
        *(float4*)&g_xpre[r*1024 + colp] = v;
    }
}

/* ================= Kernel 3: persistent cluster recurrence =================
   grid (8,16): 16 independent 8-CTA clusters, one per 64-row batch tile.
   CTA (h, bm): 64 rows x 32 units. W_hh slice (128KB) in SMEM once,
   cx in registers, hx via L2 + barrier.cluster per step.                  */
#define RNN_SMEM_FLOATS (32768 + 64*132 + 32*66 + 64*36 + 384 + 64 + 3*64)

__global__ void __launch_bounds__(256,1) __cluster_dims__(8,1,1)
rnn_all_kernel(const float* __restrict__ coords, const float* __restrict__ W_ih,
               const float* __restrict__ W_hh,   const float* __restrict__ W_out,
               const float* __restrict__ b_out,  const float* __restrict__ pitch)
{
    extern __shared__ float sm[];
    float* w_s    = sm;                    /* [256][128] c=g*32+u  : 32768 */
    float* xpre_s = w_s    + 32768;        /* [64][132]            :  8448 */
    float* hx_s   = xpre_s + 8448;         /* [32][66]             :  2112 */
    float* epi    = hx_s   + 2112;         /* [64][36]             :  2304 */
    float* crit_s = epi    + 2304;         /* [3][128]             :   384 */
    float* wo_s   = crit_s + 384;          /* [32][2]              :    64 */
    float* clo_s  = wo_s   + 64;
    float* px_s   = clo_s  + 64;
    float* py_s   = px_s   + 64;

    int h = blockIdx.x, bm = blockIdx.y;
    int tid = threadIdx.x, tb = tid & 31, tu = tid >> 5;

    /* ---- one-time loads ---- */
#pragma unroll
    for (int i = 0; i < 32; i++){
        int li = tid + i*256;              /* 8192 f4 = 256 k x 32 c4 */
        int c4 = li & 31, k = li >> 5;
        int col = (c4>>3)*256 + h*32 + (c4&7)*4;
        *(float4*)&w_s[k*128 + (c4>>3)*32 + (c4&7)*4] =
            *(const float4*)&W_hh[k*1024 + col];
    }
    if (tid < 128){
#pragma unroll
        for (int j = 0; j < 3; j++)
            crit_s[j*128 + tid] = W_ih[(172+j)*1024 + (tid>>5)*256 + h*32 + (tid&31)];
    }
    if (tid < 64){
        int u = tid >> 1, d = tid & 1;
        wo_s[tid] = W_out[((size_t)(h*32+u))*90 + 88 + d];
    }
    float ps0 = pitch[0], ps1 = pitch[1];
    float bo88 = b_out[88], bo89 = b_out[89];

    float cx[2][2][2];                     /* [row2][upair][lane] */
#pragma unroll
    for (int a=0;a<2;a++)
#pragma unroll
        for (int b=0;b<2;b++){ cx[a][b][0]=0.f; cx[a][b][1]=0.f; }

    __syncthreads();

    int prow = tid >> 3, pc4 = (tid & 7) << 2;   /* hx prefetch mapping */

    for (int t = 0; t < NSEQ; t++){
        /* ---- pred + closest distance (per batch row) ---- */
        if (tid < 64){
            int bg = bm*64 + tid;
            float px = 0.f, py = 0.f;
            if (t > 0){
                const float* pp = g_predpart[(t-1)&1];
#pragma unroll
                for (int hh = 0; hh < 8; hh++){
                    float2 v = __ldcg((const float2*)&pp[((size_t)hh*NBATCH + bg)*2]);
                    px += v.x; py += v.y;
                }
                px = (px + bo88) * ps0;
                py = (py + bo89) * ps1;
            }
            const float* cp = coords + ((size_t)bg*NSEQ + t)*88;
            float md = 3.402823e38f;
#pragma unroll
            for (int p = 0; p < 22; p++){
                float dx = px - __ldg(&cp[4*p]), dy = py - __ldg(&cp[4*p+1]);
                md = fminf(md, fmaf(dx,dx,dy*dy));
            }
            clo_s[tid] = sqrtf(md);
            px_s[tid] = px; py_s[tid] = py;
        }
        /* ---- xpre tile -> smem (coalesced) ---- */
#pragma unroll
        for (int i = 0; i < 8; i++){
            int li = tid + i*256;          /* 2048 f4 = 64 rows x 32 c4 */
            int row = li >> 5, c4 = li & 31;
            size_t r = ((size_t)(bm*64 + row))*NSEQ + t;
            float4 v = __ldcg((const float4*)&g_xpre[r*1024 + h*128 + 4*c4]);
            *(float4*)&xpre_s[row*132 + 4*c4] = v;
        }

        u64 acc2[2][4][2];
#pragma unroll
        for (int r2=0;r2<2;r2++)
#pragma unroll
            for (int g=0;g<4;g++){ acc2[r2][g][0]=0ULL; acc2[r2][g][1]=0ULL; }

        if (t > 0){
            const float* hx = g_hseq + ((size_t)(t-1)*NBATCH + bm*64)*256;
            float4 pf0 = __ldcg((const float4*)&hx[prow*256 + pc4]);
            float4 pf1 = __ldcg((const float4*)&hx[(prow+32)*256 + pc4]);
            for (int kc = 0; kc < 8; kc++){
                __syncthreads();
                hx_s[(pc4+0)*66 + prow] = pf0.x;
                hx_s[(pc4+1)*66 + prow] = pf0.y;
                hx_s[(pc4+2)*66 + prow] = pf0.z;
                hx_s[(pc4+3)*66 + prow] = pf0.w;
                hx_s[(pc4+0)*66 + prow+32] = pf1.x;
                hx_s[(pc4+1)*66 + prow+32] = pf1.y;
                hx_s[(pc4+2)*66 + prow+32] = pf1.z;
                hx_s[(pc4+3)*66 + prow+32] = pf1.w;
                __syncthreads();
                int kcn = (kc < 7) ? kc+1 : 7;
                pf0 = __ldcg((const float4*)&hx[prow*256 + kcn*32 + pc4]);
                pf1 = __ldcg((const float4*)&hx[(prow+32)*256 + kcn*32 + pc4]);
#pragma unroll
                for (int kk = 0; kk < 32; kk++){
                    u64 a2 = *(const u64*)&hx_s[kk*66 + 2*tb];
                    float alo, ahi; unpack2(a2, alo, ahi);
                    u64 a0 = pack2(alo, alo), a1 = pack2(ahi, ahi);
                    int kw = (kc*32 + kk)*128 + 4*tu;   /* FIX: chunk offset restored */
#pragma unroll
                    for (int g = 0; g < 4; g++){
                        u64 w0 = *(const u64*)&w_s[kw + g*32];
                        u64 w1 = *(const u64*)&w_s[kw + g*32 + 2];
                        acc2[0][g][0] = fma2(a0, w0, acc2[0][g][0]);
                        acc2[0][g][1] = fma2(a0, w1, acc2[0][g][1]);
                        acc2[1][g][0] = fma2(a1, w0, acc2[1][g][0]);
                        acc2[1][g][1] = fma2(a1, w1, acc2[1][g][1]);
                    }
                }
            }
        }
        __syncthreads();

        /* ---- LSTM pointwise: thread owns 2 rows x 4 units x 4 gates ---- */
#pragma unroll
        for (int r2 = 0; r2 < 2; r2++){
            int row = 2*tb + r2;
            float clo = clo_s[row], ppx = px_s[row], ppy = py_s[row];
#pragma unroll
            for (int up = 0; up < 2; up++){
                int c0 = 4*tu + 2*up;          /* local unit index */
                float gl[4][2];
#pragma unroll
                for (int g = 0; g < 4; g++){
                    float lo, hi; unpack2(acc2[r2][g][up], lo, hi);
                    int c = g*32 + c0;
                    gl[g][0] = lo + xpre_s[row*132 + c]
                             + clo*crit_s[c]   + ppx*crit_s[128+c]   + ppy*crit_s[256+c];
                    gl[g][1] = hi + xpre_s[row*132 + c+1]
                             + clo*crit_s[c+1] + ppx*crit_s[128+c+1] + ppy*crit_s[256+c+1];
                }
                float c20 = sigmoidf_(gl[1][0])*cx[r2][up][0] + sigmoidf_(gl[0][0])*tanhf(gl[2][0]);
                float c21 = sigmoidf_(gl[1][1])*cx[r2][up][1] + sigmoidf_(gl[0][1])*tanhf(gl[2][1]);
                float h20 = sigmoidf_(gl[3][0])*tanhf(c20);
                float h21 = sigmoidf_(gl[3][1])*tanhf(c21);
                cx[r2][up][0] = c20; cx[r2][up][1] = c21;
                epi[row*36 + c0]     = h20;
                epi[row*36 + c0 + 1] = h21;
            }
        }
        __syncthreads();

        /* ---- hseq store (coalesced) ---- */
        {
            float* hout = g_hseq + ((size_t)t*NBATCH + bm*64)*256 + h*32;
#pragma unroll
            for (int i = 0; i < 2; i++){
                int li = tid + i*256;      /* 512 f4 = 64 rows x 8 f4 */
                int row = li >> 3, c4 = li & 7;
                float4 v = make_float4(epi[row*36 + 4*c4],   epi[row*36 + 4*c4+1],
                                       epi[row*36 + 4*c4+2], epi[row*36 + 4*c4+3]);
                *(float4*)&hout[row*256 + 4*c4] = v;
            }
        }
        /* ---- pred partials for step t+1 ---- */
        if (tid < 64){
            int bg = bm*64 + tid;
            float px = 0.f, py = 0.f;
#pragma unroll
            for (int u = 0; u < 32; u++){
                float hv = epi[tid*36 + u];
                px = fmaf(hv, wo_s[2*u],   px);
                py = fmaf(hv, wo_s[2*u+1], py);
            }
            *(float2*)&g_predpart[t&1][((size_t)h*NBATCH + bg)*2] = make_float2(px, py);
        }

        /* ---- cluster barrier: release (fence) -> arrive/wait -> acquire (fence) ---- */
        __threadfence();
        asm volatile("barrier.cluster.arrive.aligned;" ::: "memory");
        asm volatile("barrier.cluster.wait.aligned;"   ::: "memory");
        __threadfence();
    }
}

/* ================= Kernel 4: output head GEMM ================= */
__global__ void __launch_bounds__(256) out_kernel(
    const float* __restrict__ W_out, const float* __restrict__ b_out,
    const float* __restrict__ pitch, float* __restrict__ out)
{
    size_t r0 = (size_t)blockIdx.x * 64;
    int tid = threadIdx.x;
    int tx = tid & 15, ty = tid >> 4;

    __shared__ float a_s[32*68];
    __shared__ float w_s[32*96];

    float acc[4][6];
#pragma unroll
    for (int bi=0;bi<4;bi++)
#pragma unroll
        for (int ci=0;ci<6;ci++) acc[bi][ci]=0.f;

    for (int k0 = 0; k0 < 256; k0 += 32){
#pragma unroll
        for (int i = 0; i < 8; i++){
            int li = tid + i*256;
            int kk = li & 31, row = li >> 5;
            size_t r = r0 + row;
            int t = (int)(r % NSEQ), b = (int)(r / NSEQ);
            a_s[kk*68 + row] = g_hseq[((size_t)t*NBATCH + b)*256 + k0 + kk];
        }
#pragma unroll
        for (int i = 0; i < 12; i++){
            int li = tid + i*256;
            int n = li % 96, kk = li / 96;
            w_s[kk*96 + n] = (n < 90) ? W_out[(k0+kk)*90 + n] : 0.f;
        }
        __syncthreads();
#pragma unroll
        for (int kk = 0; kk < 32; kk++){
            float4 a = *(const float4*)&a_s[kk*68 + 4*ty];
            float w[6];
#pragma unroll
            for (int ci = 0; ci < 6; ci++) w[ci] = w_s[kk*96 + 6*tx + ci];
#pragma unroll
            for (int ci = 0; ci < 6; ci++){
                acc[0][ci] = fmaf(a.x, w[ci], acc[0][ci]);
                acc[1][ci] = fmaf(a.y, w[ci], acc[1][ci]);
                acc[2][ci] = fmaf(a.z, w[ci], acc[2][ci]);
                acc[3][ci] = fmaf(a.w, w[ci], acc[3][ci]);
            }
        }
        __syncthreads();
    }
#pragma unroll
    for (int bi = 0; bi < 4; bi++){
        size_t r = r0 + 4*ty + bi;
#pragma unroll
        for (int ci = 0; ci < 6; ci++){
            int n = 6*tx + ci;
            if (n < 90)
                out[r*90 + n] = (acc[bi][ci] + b_out[n]) * pitch[n & 1];
        }
    }
}

/* ================= host launcher ================= */
extern "C" void kernel_launch(void* const* d_in, const int* in_sizes, int n_in,
                              void* d_out, int out_size)
{
    const float* coords = (const float*)d_in[0];
    const float* pitch  = (const float*)d_in[1];
    const float* W_e1   = (const float*)d_in[2];
    const float* b_e1   = (const float*)d_in[3];
    const float* W_e2   = (const float*)d_in[4];
    const float* b_e2   = (const float*)d_in[5];
    const float* W_ih   = (const float*)d_in[6];
    const float* b_ih   = (const float*)d_in[7];
    const float* W_hh   = (const float*)d_in[8];
    const float* b_hh   = (const float*)d_in[9];
    const float* W_out  = (const float*)d_in[10];
    const float* b_out  = (const float*)d_in[11];
    float* out = (float*)d_out;

    size_t xpre_smem = 14592u * sizeof(float);             /* 58,368 B  */
    size_t rnn_smem  = (size_t)RNN_SMEM_FLOATS * sizeof(float); /* ~185 KB */
    static int attr_done = 0;
    if (!attr_done){
        cudaFuncSetAttribute(xpre_kernel, cudaFuncAttributeMaxDynamicSharedMemorySize,
                             (int)xpre_smem);
        cudaFuncSetAttribute(rnn_all_kernel, cudaFuncAttributeMaxDynamicSharedMemorySize,
                             (int)rnn_smem);
        attr_done = 1;
    }

    enc_kernel<<<NROWS/4, 256>>>(coords, W_e1, b_e1, W_e2, b_e2);
    xpre_kernel<<<dim3(16, NROWS/128), 256, xpre_smem>>>(coords, W_ih, b_ih, b_hh);
    rnn_all_kernel<<<dim3(8,16), 256, rnn_smem>>>(coords, W_ih, W_hh, W_out, b_out, pitch);
    out_kernel<<<NROWS/64, 256>>>(W_out, b_out, pitch, out);
}